// round 1
// baseline (speedup 1.0000x reference)
#include <cuda_runtime.h>
#include <cuda_bf16.h>

#define NN 100000
#define EE 3200000

// ---------------- scratch (device globals; no allocations) ----------------
__device__ int   g_src[EE];
__device__ int   g_dst[EE];
__device__ float g_xl1[NN * 16];
__device__ float g_xr1[NN * 16];
__device__ float g_logits1[EE * 4];
__device__ float g_m1[NN * 4];
__device__ float g_den1[NN * 4];
__device__ float g_agg1[NN * 16];
__device__ float g_xl2[NN * 8];
__device__ float g_xr2[NN * 8];
__device__ float g_logits2[EE];
__device__ float g_m2[NN];
__device__ float g_den2[NN];
__device__ float g_agg2[NN * 8];
__device__ int   g_is64;

// ---------------- helpers ----------------
__device__ __forceinline__ float lrelu02(float x) {
    // leaky_relu slope 0.2: for x>0, x > 0.2x; for x<0, 0.2x > x
    return fmaxf(x, 0.2f * x);
}

__device__ __forceinline__ void atomicMaxF(float* addr, float v) {
    if (v >= 0.0f)
        atomicMax((int*)addr, __float_as_int(v));
    else
        atomicMin((unsigned int*)addr, __float_as_uint(v));
}

__device__ __forceinline__ void redAdd4(float* addr, float a, float b, float c, float d) {
    asm volatile("red.global.add.v4.f32 [%0], {%1,%2,%3,%4};"
                 :: "l"(addr), "f"(a), "f"(b), "f"(c), "f"(d) : "memory");
}

// ---------------- K0: detect edge_index dtype ----------------
__global__ void detect_kernel(const long long* __restrict__ ei) {
    int t = threadIdx.x;
    int bad = 0;
    for (int i = t; i < 2048; i += 256) {
        long long v = ei[i];
        if (v < 0 || v >= (long long)NN) bad = 1;
    }
    bad = __syncthreads_or(bad);
    if (t == 0) g_is64 = bad ? 0 : 1;   // bad => values out of range => really int32
}

// ---------------- K1: convert edge_index -> int32 src/dst ----------------
__global__ void convert_kernel(const void* __restrict__ ei) {
    int i = blockIdx.x * blockDim.x + threadIdx.x;
    if (i >= EE) return;
    int s, d;
    if (g_is64) {
        const long long* p = (const long long*)ei;
        s = (int)p[i];
        d = (int)p[EE + i];
    } else {
        const int* p = (const int*)ei;
        s = p[i];
        d = p[EE + i];
    }
    g_src[i] = s;
    g_dst[i] = d;
}

// ---------------- K2: init accumulators ----------------
__global__ void init_kernel() {
    int i = blockIdx.x * blockDim.x + threadIdx.x;
    if (i < NN * 4)  { g_m1[i] = -3.402823e38f; g_den1[i] = 0.0f; }
    if (i < NN * 16) { g_agg1[i] = 0.0f; }
    if (i < NN)      { g_m2[i] = -3.402823e38f; g_den2[i] = 0.0f; }
    if (i < NN * 8)  { g_agg2[i] = 0.0f; }
}

// ---------------- K3: GEMM1: xl1 = x@W1l, xr1 = x@W1r (fused, 32 output cols) ----------------
__global__ void gemm1_kernel(const float* __restrict__ x,
                             const float* __restrict__ W1l,
                             const float* __restrict__ W1r) {
    __shared__ float Ws[256 * 32];     // combined weights [k][c], c<16 -> Wl, else Wr
    __shared__ float xs[64 * 65];      // 64 nodes x 64 k (padded)

    int t = threadIdx.x;
    for (int i = t; i < 256 * 16; i += 256) {
        int k = i >> 4, c = i & 15;
        Ws[k * 32 + c]      = W1l[i];
        Ws[k * 32 + 16 + c] = W1r[i];
    }

    int nodeBase = blockIdx.x * 64;
    int c    = t & 31;   // output column
    int wrow = t >> 5;   // warp id 0..7, owns 8 nodes

    float acc[8];
#pragma unroll
    for (int m = 0; m < 8; m++) acc[m] = 0.0f;

    for (int kc = 0; kc < 256; kc += 64) {
        __syncthreads();
        for (int i = t; i < 64 * 64; i += 256) {
            int row = i >> 6, col = i & 63;
            int node = nodeBase + row;
            xs[row * 65 + col] = (node < NN) ? x[node * 256 + kc + col] : 0.0f;
        }
        __syncthreads();
#pragma unroll 8
        for (int k = 0; k < 64; k++) {
            float wv = Ws[(kc + k) * 32 + c];
#pragma unroll
            for (int m = 0; m < 8; m++) {
                acc[m] += xs[(wrow * 8 + m) * 65 + k] * wv;
            }
        }
    }

#pragma unroll
    for (int m = 0; m < 8; m++) {
        int node = nodeBase + wrow * 8 + m;
        if (node < NN) {
            if (c < 16) g_xl1[node * 16 + c] = acc[m];
            else        g_xr1[node * 16 + (c - 16)] = acc[m];
        }
    }
}

// ---------------- K4: edge pass A1: logits + segment max ----------------
__global__ void edgeA1_kernel(const float* __restrict__ a1) {
    int e = blockIdx.x * blockDim.x + threadIdx.x;
    if (e >= EE) return;
    int s = g_src[e], d = g_dst[e];

    const float4* xl = (const float4*)(g_xl1 + s * 16);
    const float4* xr = (const float4*)(g_xr1 + d * 16);

    float lg[4];
#pragma unroll
    for (int h = 0; h < 4; h++) {
        float4 l = xl[h];
        float4 r = xr[h];
        float a0 = __ldg(a1 + h * 4 + 0);
        float a_1 = __ldg(a1 + h * 4 + 1);
        float a2 = __ldg(a1 + h * 4 + 2);
        float a3 = __ldg(a1 + h * 4 + 3);
        lg[h] = a0 * lrelu02(l.x + r.x) + a_1 * lrelu02(l.y + r.y)
              + a2 * lrelu02(l.z + r.z) + a3 * lrelu02(l.w + r.w);
    }
    *(float4*)(g_logits1 + e * 4) = make_float4(lg[0], lg[1], lg[2], lg[3]);

#pragma unroll
    for (int h = 0; h < 4; h++) atomicMaxF(&g_m1[d * 4 + h], lg[h]);
}

// ---------------- K5: edge pass B1: exp + segment sum ----------------
__global__ void edgeB1_kernel() {
    int e = blockIdx.x * blockDim.x + threadIdx.x;
    if (e >= EE) return;
    int d = g_dst[e];
    float4 lg = *(const float4*)(g_logits1 + e * 4);
    float4 m  = *(const float4*)(g_m1 + d * 4);
    float4 ex;
    ex.x = __expf(lg.x - m.x);
    ex.y = __expf(lg.y - m.y);
    ex.z = __expf(lg.z - m.z);
    ex.w = __expf(lg.w - m.w);
    *(float4*)(g_logits1 + e * 4) = ex;
    redAdd4(g_den1 + d * 4, ex.x, ex.y, ex.z, ex.w);
}

// ---------------- K6: edge pass C1: weighted scatter ----------------
__global__ void edgeC1_kernel() {
    int e = blockIdx.x * blockDim.x + threadIdx.x;
    if (e >= EE) return;
    int s = g_src[e], d = g_dst[e];
    float4 ex  = *(const float4*)(g_logits1 + e * 4);
    float4 den = *(const float4*)(g_den1 + d * 4);
    float w0 = ex.x / (den.x + 1e-16f);
    float w1 = ex.y / (den.y + 1e-16f);
    float w2 = ex.z / (den.z + 1e-16f);
    float w3 = ex.w / (den.w + 1e-16f);

    const float4* xl = (const float4*)(g_xl1 + s * 16);
    float4 v0 = xl[0], v1 = xl[1], v2 = xl[2], v3 = xl[3];

    float* out = g_agg1 + d * 16;
    redAdd4(out + 0,  w0 * v0.x, w0 * v0.y, w0 * v0.z, w0 * v0.w);
    redAdd4(out + 4,  w1 * v1.x, w1 * v1.y, w1 * v1.z, w1 * v1.w);
    redAdd4(out + 8,  w2 * v2.x, w2 * v2.y, w2 * v2.z, w2 * v2.w);
    redAdd4(out + 12, w3 * v3.x, w3 * v3.y, w3 * v3.z, w3 * v3.w);
}

// ---------------- K7: node layer-2: elu + bias + tiny GEMM (16->8 x2) ----------------
__global__ void node2_kernel(const float* __restrict__ b1,
                             const float* __restrict__ W2l,
                             const float* __restrict__ W2r) {
    __shared__ float sWl[128], sWr[128], sb1[16];
    int t = threadIdx.x;
    if (t < 128) { sWl[t] = W2l[t]; sWr[t] = W2r[t]; }
    if (t < 16)  { sb1[t] = b1[t]; }
    __syncthreads();

    int n = blockIdx.x * blockDim.x + t;
    if (n >= NN) return;

    float v[16];
    const float4* ap = (const float4*)(g_agg1 + n * 16);
#pragma unroll
    for (int i = 0; i < 4; i++) {
        float4 a = ap[i];
        float t0 = a.x + sb1[i * 4 + 0];
        float t1 = a.y + sb1[i * 4 + 1];
        float t2 = a.z + sb1[i * 4 + 2];
        float t3 = a.w + sb1[i * 4 + 3];
        v[i * 4 + 0] = (t0 > 0.0f) ? t0 : (__expf(t0) - 1.0f);
        v[i * 4 + 1] = (t1 > 0.0f) ? t1 : (__expf(t1) - 1.0f);
        v[i * 4 + 2] = (t2 > 0.0f) ? t2 : (__expf(t2) - 1.0f);
        v[i * 4 + 3] = (t3 > 0.0f) ? t3 : (__expf(t3) - 1.0f);
    }

    float ol[8], orr[8];
#pragma unroll
    for (int c = 0; c < 8; c++) { ol[c] = 0.0f; orr[c] = 0.0f; }
#pragma unroll
    for (int k = 0; k < 16; k++) {
#pragma unroll
        for (int c = 0; c < 8; c++) {
            ol[c]  += v[k] * sWl[k * 8 + c];
            orr[c] += v[k] * sWr[k * 8 + c];
        }
    }
    float4* pl = (float4*)(g_xl2 + n * 8);
    float4* pr = (float4*)(g_xr2 + n * 8);
    pl[0] = make_float4(ol[0], ol[1], ol[2], ol[3]);
    pl[1] = make_float4(ol[4], ol[5], ol[6], ol[7]);
    pr[0] = make_float4(orr[0], orr[1], orr[2], orr[3]);
    pr[1] = make_float4(orr[4], orr[5], orr[6], orr[7]);
}

// ---------------- K8: edge pass A2 ----------------
__global__ void edgeA2_kernel(const float* __restrict__ a2) {
    int e = blockIdx.x * blockDim.x + threadIdx.x;
    if (e >= EE) return;
    int s = g_src[e], d = g_dst[e];
    const float4* xl = (const float4*)(g_xl2 + s * 8);
    const float4* xr = (const float4*)(g_xr2 + d * 8);
    float lg = 0.0f;
#pragma unroll
    for (int i = 0; i < 2; i++) {
        float4 l = xl[i];
        float4 r = xr[i];
        lg += __ldg(a2 + i * 4 + 0) * lrelu02(l.x + r.x);
        lg += __ldg(a2 + i * 4 + 1) * lrelu02(l.y + r.y);
        lg += __ldg(a2 + i * 4 + 2) * lrelu02(l.z + r.z);
        lg += __ldg(a2 + i * 4 + 3) * lrelu02(l.w + r.w);
    }
    g_logits2[e] = lg;
    atomicMaxF(&g_m2[d], lg);
}

// ---------------- K9: edge pass B2 ----------------
__global__ void edgeB2_kernel() {
    int e = blockIdx.x * blockDim.x + threadIdx.x;
    if (e >= EE) return;
    int d = g_dst[e];
    float ex = __expf(g_logits2[e] - g_m2[d]);
    g_logits2[e] = ex;
    atomicAdd(&g_den2[d], ex);
}

// ---------------- K10: edge pass C2 ----------------
__global__ void edgeC2_kernel() {
    int e = blockIdx.x * blockDim.x + threadIdx.x;
    if (e >= EE) return;
    int s = g_src[e], d = g_dst[e];
    float w = g_logits2[e] / (g_den2[d] + 1e-16f);
    const float4* xl = (const float4*)(g_xl2 + s * 8);
    float4 v0 = xl[0], v1 = xl[1];
    float* out = g_agg2 + d * 8;
    redAdd4(out + 0, w * v0.x, w * v0.y, w * v0.z, w * v0.w);
    redAdd4(out + 4, w * v1.x, w * v1.y, w * v1.z, w * v1.w);
}

// ---------------- K11: final sigmoid ----------------
__global__ void final_kernel(const float* __restrict__ b2, float* __restrict__ out) {
    int i = blockIdx.x * blockDim.x + threadIdx.x;
    if (i >= NN * 8) return;
    float v = g_agg2[i] + __ldg(b2 + (i & 7));
    out[i] = 1.0f / (1.0f + __expf(-v));
}

// ---------------- launch ----------------
extern "C" void kernel_launch(void* const* d_in, const int* in_sizes, int n_in,
                              void* d_out, int out_size) {
    const float* x   = (const float*)d_in[0];
    const void*  ei  = d_in[1];
    const float* W1l = (const float*)d_in[2];
    const float* W1r = (const float*)d_in[3];
    const float* a1  = (const float*)d_in[4];
    const float* b1  = (const float*)d_in[5];
    const float* W2l = (const float*)d_in[6];
    const float* W2r = (const float*)d_in[7];
    const float* a2  = (const float*)d_in[8];
    const float* b2  = (const float*)d_in[9];
    float* out = (float*)d_out;

    const int EB = (EE + 255) / 256;

    detect_kernel<<<1, 256>>>((const long long*)ei);
    convert_kernel<<<EB, 256>>>(ei);
    init_kernel<<<(NN * 16 + 255) / 256, 256>>>();
    gemm1_kernel<<<(NN + 63) / 64, 256>>>(x, W1l, W1r);
    edgeA1_kernel<<<EB, 256>>>(a1);
    edgeB1_kernel<<<EB, 256>>>();
    edgeC1_kernel<<<EB, 256>>>();
    node2_kernel<<<(NN + 255) / 256, 256>>>(b1, W2l, W2r);
    edgeA2_kernel<<<EB, 256>>>(a2);
    edgeB2_kernel<<<EB, 256>>>();
    edgeC2_kernel<<<EB, 256>>>();
    final_kernel<<<(NN * 8 + 255) / 256, 256>>>(b2, out);
}

// round 2
// speedup vs baseline: 1.5971x; 1.5971x over previous
#include <cuda_runtime.h>
#include <cuda_bf16.h>

#define NN 100000
#define EE 3200000

// ---------------- scratch (device globals; no allocations) ----------------
__device__ int   g_src[EE];
__device__ int   g_dst[EE];
__device__ float g_xl1[NN * 16];
__device__ float g_xr1[NN * 16];
__device__ float g_den1[NN * 4];
__device__ float g_agg1[NN * 16];
__device__ float g_xl2[NN * 8];
__device__ float g_xr2[NN * 8];
__device__ float g_den2[NN];
__device__ float g_agg2[NN * 8];
__device__ int   g_is64;

// ---------------- helpers ----------------
__device__ __forceinline__ float lrelu02(float x) {
    return fmaxf(x, 0.2f * x);
}

__device__ __forceinline__ void redAdd4(float* addr, float a, float b, float c, float d) {
    asm volatile("red.global.add.v4.f32 [%0], {%1,%2,%3,%4};"
                 :: "l"(addr), "f"(a), "f"(b), "f"(c), "f"(d) : "memory");
}

// ---------------- K0: detect edge_index dtype ----------------
__global__ void detect_kernel(const long long* __restrict__ ei) {
    int t = threadIdx.x;
    int bad = 0;
    for (int i = t; i < 2048; i += 256) {
        long long v = ei[i];
        if (v < 0 || v >= (long long)NN) bad = 1;
    }
    bad = __syncthreads_or(bad);
    if (t == 0) g_is64 = bad ? 0 : 1;
}

// ---------------- K1: convert edge_index -> int32 src/dst ----------------
__global__ void convert_kernel(const void* __restrict__ ei) {
    int i = blockIdx.x * blockDim.x + threadIdx.x;
    if (i >= EE) return;
    int s, d;
    if (g_is64) {
        const long long* p = (const long long*)ei;
        s = (int)p[i];
        d = (int)p[EE + i];
    } else {
        const int* p = (const int*)ei;
        s = p[i];
        d = p[EE + i];
    }
    g_src[i] = s;
    g_dst[i] = d;
}

// ---------------- K2: init accumulators ----------------
__global__ void init_kernel() {
    int i = blockIdx.x * blockDim.x + threadIdx.x;
    if (i < NN * 4)  { g_den1[i] = 0.0f; }
    if (i < NN * 16) { g_agg1[i] = 0.0f; }
    if (i < NN)      { g_den2[i] = 0.0f; }
    if (i < NN * 8)  { g_agg2[i] = 0.0f; }
}

// ---------------- K3: GEMM1 (register-tiled 4 nodes x 8 cols / thread) ----------
// Block: 256 threads, 256-node tile, all 32 output cols (16 Wl | 16 Wr).
// Dynamic smem: Ws[256*32] then xs[256 nodes][65 (64 k + pad)].
#define G_NODES 256
#define G_KC    64
#define G_SMEM  ((256 * 32 + G_NODES * 65) * sizeof(float))

__global__ void gemm1_kernel(const float* __restrict__ x,
                             const float* __restrict__ W1l,
                             const float* __restrict__ W1r) {
    extern __shared__ float smem[];
    float* Ws = smem;                 // [k][32]
    float* xs = smem + 256 * 32;      // [node][65]

    int t = threadIdx.x;
    // Load weights interleaved: col c<16 -> W1l, c>=16 -> W1r
    for (int i = t; i < 256 * 16; i += 256) {
        int k = i >> 4, c = i & 15;
        Ws[k * 32 + c]      = W1l[i];
        Ws[k * 32 + 16 + c] = W1r[i];
    }

    int nodeBase = blockIdx.x * G_NODES;
    int cg = (t & 3) * 8;        // col base: 0,8,16,24
    int ng = (t >> 2) * 4;       // node base within tile: 0..252

    float acc[4][8];
#pragma unroll
    for (int m = 0; m < 4; m++)
#pragma unroll
        for (int c = 0; c < 8; c++) acc[m][c] = 0.0f;

    for (int kc = 0; kc < 256; kc += G_KC) {
        __syncthreads();
        // Load 256 nodes x 64 k chunk. 16 consecutive threads cover one node row.
#pragma unroll
        for (int it = 0; it < (G_NODES * G_KC / 4) / 256; it++) {  // 16 iters
            int idx = t + 256 * it;
            int node = idx >> 4;
            int k4 = (idx & 15) * 4;
            int gnode = nodeBase + node;
            float4 v = (gnode < NN)
                ? *(const float4*)(x + (size_t)gnode * 256 + kc + k4)
                : make_float4(0.f, 0.f, 0.f, 0.f);
            float* p = xs + node * 65 + k4;
            p[0] = v.x; p[1] = v.y; p[2] = v.z; p[3] = v.w;
        }
        __syncthreads();

#pragma unroll 4
        for (int k = 0; k < G_KC; k++) {
            float w[8];
            *(float4*)&w[0] = *(const float4*)&Ws[(kc + k) * 32 + cg];
            *(float4*)&w[4] = *(const float4*)&Ws[(kc + k) * 32 + cg + 4];
            float xm[4];
#pragma unroll
            for (int m = 0; m < 4; m++) xm[m] = xs[(ng + m) * 65 + k];
#pragma unroll
            for (int m = 0; m < 4; m++)
#pragma unroll
                for (int c = 0; c < 8; c++)
                    acc[m][c] = fmaf(xm[m], w[c], acc[m][c]);
        }
    }

#pragma unroll
    for (int m = 0; m < 4; m++) {
        int node = nodeBase + ng + m;
        if (node < NN) {
            float* dstp = (cg < 16) ? (g_xl1 + node * 16 + cg)
                                    : (g_xr1 + node * 16 + (cg - 16));
            *(float4*)(dstp)     = make_float4(acc[m][0], acc[m][1], acc[m][2], acc[m][3]);
            *(float4*)(dstp + 4) = make_float4(acc[m][4], acc[m][5], acc[m][6], acc[m][7]);
        }
    }
}

// ---------------- K4: fused edge pass, layer 1 ----------------
// No max subtraction (logits are O(1)); no normalized alpha (divide at node).
// Per edge: ex_h = exp(logit_h); den1[d] += ex; agg1[d] += ex_h * xl1[s].
__global__ void edge1_kernel(const float* __restrict__ a1) {
    int e = blockIdx.x * blockDim.x + threadIdx.x;
    if (e >= EE) return;
    int s = g_src[e], d = g_dst[e];

    const float4* xl = (const float4*)(g_xl1 + s * 16);
    const float4* xr = (const float4*)(g_xr1 + d * 16);

    float4 l[4], r[4];
#pragma unroll
    for (int h = 0; h < 4; h++) { l[h] = __ldg(xl + h); r[h] = __ldg(xr + h); }

    float ex[4];
#pragma unroll
    for (int h = 0; h < 4; h++) {
        float a0 = __ldg(a1 + h * 4 + 0);
        float a_1 = __ldg(a1 + h * 4 + 1);
        float a2 = __ldg(a1 + h * 4 + 2);
        float a3 = __ldg(a1 + h * 4 + 3);
        float lg = a0 * lrelu02(l[h].x + r[h].x) + a_1 * lrelu02(l[h].y + r[h].y)
                 + a2 * lrelu02(l[h].z + r[h].z) + a3 * lrelu02(l[h].w + r[h].w);
        ex[h] = __expf(lg);
    }

    redAdd4(g_den1 + d * 4, ex[0], ex[1], ex[2], ex[3]);
    float* out = g_agg1 + d * 16;
#pragma unroll
    for (int h = 0; h < 4; h++)
        redAdd4(out + 4 * h, ex[h] * l[h].x, ex[h] * l[h].y, ex[h] * l[h].z, ex[h] * l[h].w);
}

// ---------------- K5: node layer-2: normalize + bias + elu + tiny GEMM ------
__global__ void node2_kernel(const float* __restrict__ b1,
                             const float* __restrict__ W2l,
                             const float* __restrict__ W2r) {
    __shared__ float sWl[128], sWr[128], sb1[16];
    int t = threadIdx.x;
    if (t < 128) { sWl[t] = W2l[t]; sWr[t] = W2r[t]; }
    if (t < 16)  { sb1[t] = b1[t]; }
    __syncthreads();

    int n = blockIdx.x * blockDim.x + t;
    if (n >= NN) return;

    float4 den = *(const float4*)(g_den1 + n * 4);
    float inv[4] = { 1.0f / (den.x + 1e-16f), 1.0f / (den.y + 1e-16f),
                     1.0f / (den.z + 1e-16f), 1.0f / (den.w + 1e-16f) };

    float v[16];
    const float4* ap = (const float4*)(g_agg1 + n * 16);
#pragma unroll
    for (int h = 0; h < 4; h++) {
        float4 a = ap[h];
        float t0 = a.x * inv[h] + sb1[h * 4 + 0];
        float t1 = a.y * inv[h] + sb1[h * 4 + 1];
        float t2 = a.z * inv[h] + sb1[h * 4 + 2];
        float t3 = a.w * inv[h] + sb1[h * 4 + 3];
        v[h * 4 + 0] = (t0 > 0.0f) ? t0 : (__expf(t0) - 1.0f);
        v[h * 4 + 1] = (t1 > 0.0f) ? t1 : (__expf(t1) - 1.0f);
        v[h * 4 + 2] = (t2 > 0.0f) ? t2 : (__expf(t2) - 1.0f);
        v[h * 4 + 3] = (t3 > 0.0f) ? t3 : (__expf(t3) - 1.0f);
    }

    float ol[8], orr[8];
#pragma unroll
    for (int c = 0; c < 8; c++) { ol[c] = 0.0f; orr[c] = 0.0f; }
#pragma unroll
    for (int k = 0; k < 16; k++) {
#pragma unroll
        for (int c = 0; c < 8; c++) {
            ol[c]  = fmaf(v[k], sWl[k * 8 + c], ol[c]);
            orr[c] = fmaf(v[k], sWr[k * 8 + c], orr[c]);
        }
    }
    float4* pl = (float4*)(g_xl2 + n * 8);
    float4* pr = (float4*)(g_xr2 + n * 8);
    pl[0] = make_float4(ol[0], ol[1], ol[2], ol[3]);
    pl[1] = make_float4(ol[4], ol[5], ol[6], ol[7]);
    pr[0] = make_float4(orr[0], orr[1], orr[2], orr[3]);
    pr[1] = make_float4(orr[4], orr[5], orr[6], orr[7]);
}

// ---------------- K6: fused edge pass, layer 2 ----------------
__global__ void edge2_kernel(const float* __restrict__ a2) {
    int e = blockIdx.x * blockDim.x + threadIdx.x;
    if (e >= EE) return;
    int s = g_src[e], d = g_dst[e];
    const float4* xl = (const float4*)(g_xl2 + s * 8);
    const float4* xr = (const float4*)(g_xr2 + d * 8);
    float4 l0 = __ldg(xl), l1 = __ldg(xl + 1);
    float4 r0 = __ldg(xr), r1 = __ldg(xr + 1);

    float lg = __ldg(a2 + 0) * lrelu02(l0.x + r0.x)
             + __ldg(a2 + 1) * lrelu02(l0.y + r0.y)
             + __ldg(a2 + 2) * lrelu02(l0.z + r0.z)
             + __ldg(a2 + 3) * lrelu02(l0.w + r0.w)
             + __ldg(a2 + 4) * lrelu02(l1.x + r1.x)
             + __ldg(a2 + 5) * lrelu02(l1.y + r1.y)
             + __ldg(a2 + 6) * lrelu02(l1.z + r1.z)
             + __ldg(a2 + 7) * lrelu02(l1.w + r1.w);
    float ex = __expf(lg);

    atomicAdd(&g_den2[d], ex);
    float* out = g_agg2 + d * 8;
    redAdd4(out + 0, ex * l0.x, ex * l0.y, ex * l0.z, ex * l0.w);
    redAdd4(out + 4, ex * l1.x, ex * l1.y, ex * l1.z, ex * l1.w);
}

// ---------------- K7: final: normalize + bias + sigmoid ----------------
__global__ void final_kernel(const float* __restrict__ b2, float* __restrict__ out) {
    int i = blockIdx.x * blockDim.x + threadIdx.x;
    if (i >= NN * 8) return;
    float den = g_den2[i >> 3];
    float v = g_agg2[i] / (den + 1e-16f) + __ldg(b2 + (i & 7));
    out[i] = 1.0f / (1.0f + __expf(-v));
}

// ---------------- launch ----------------
extern "C" void kernel_launch(void* const* d_in, const int* in_sizes, int n_in,
                              void* d_out, int out_size) {
    const float* x   = (const float*)d_in[0];
    const void*  ei  = d_in[1];
    const float* W1l = (const float*)d_in[2];
    const float* W1r = (const float*)d_in[3];
    const float* a1  = (const float*)d_in[4];
    const float* b1  = (const float*)d_in[5];
    const float* W2l = (const float*)d_in[6];
    const float* W2r = (const float*)d_in[7];
    const float* a2  = (const float*)d_in[8];
    const float* b2  = (const float*)d_in[9];
    float* out = (float*)d_out;

    static bool configured = false;
    if (!configured) {
        cudaFuncSetAttribute(gemm1_kernel,
                             cudaFuncAttributeMaxDynamicSharedMemorySize,
                             (int)G_SMEM);
        configured = true;
    }

    const int EB = (EE + 255) / 256;

    detect_kernel<<<1, 256>>>((const long long*)ei);
    convert_kernel<<<EB, 256>>>(ei);
    init_kernel<<<(NN * 16 + 255) / 256, 256>>>();
    gemm1_kernel<<<(NN + G_NODES - 1) / G_NODES, 256, G_SMEM>>>(x, W1l, W1r);
    edge1_kernel<<<EB, 256>>>(a1);
    node2_kernel<<<(NN + 255) / 256, 256>>>(b1, W2l, W2r);
    edge2_kernel<<<EB, 256>>>(a2);
    final_kernel<<<(NN * 8 + 255) / 256, 256>>>(b2, out);
}

// round 3
// speedup vs baseline: 2.0481x; 1.2824x over previous
#include <cuda_runtime.h>
#include <cuda_bf16.h>

#define NN 100000
#define EE 3200000
#define SCAN_BLOCKS 98   // ceil(NN/1024)

// ---------------- scratch (device globals; no allocations) ----------------
__device__ int   g_src[EE];
__device__ int   g_dst[EE];
__device__ int   g_esrc[EE];        // src sorted by dst (CSR)
__device__ int   g_cnt[NN];
__device__ int   g_row[NN + 1];
__device__ int   g_pos[NN];
__device__ int   g_bsum[SCAN_BLOCKS];
__device__ int   g_boff[SCAN_BLOCKS];
__device__ float g_xl1[NN * 16];
__device__ float g_xr1[NN * 16];
__device__ float g_agg1[NN * 16];   // normalized attention output, layer 1
__device__ float g_xl2[NN * 8];
__device__ float g_xr2[NN * 8];
__device__ int   g_is64;

// ---------------- helpers ----------------
__device__ __forceinline__ float lrelu02(float x) {
    return fmaxf(x, 0.2f * x);
}

// ---------------- K0: detect edge_index dtype ----------------
__global__ void detect_kernel(const long long* __restrict__ ei) {
    int t = threadIdx.x;
    int bad = 0;
    for (int i = t; i < 2048; i += 256) {
        long long v = ei[i];
        if (v < 0 || v >= (long long)NN) bad = 1;
    }
    bad = __syncthreads_or(bad);
    if (t == 0) g_is64 = bad ? 0 : 1;
}

// ---------------- K1: zero histogram ----------------
__global__ void zero_cnt_kernel() {
    int i = blockIdx.x * blockDim.x + threadIdx.x;
    if (i < NN) g_cnt[i] = 0;
}

// ---------------- K2: convert edge_index -> int32 + histogram ----------------
__global__ void convert_hist_kernel(const void* __restrict__ ei) {
    int i = blockIdx.x * blockDim.x + threadIdx.x;
    if (i >= EE) return;
    int s, d;
    if (g_is64) {
        const long long* p = (const long long*)ei;
        s = (int)p[i];
        d = (int)p[EE + i];
    } else {
        const int* p = (const int*)ei;
        s = p[i];
        d = p[EE + i];
    }
    g_src[i] = s;
    g_dst[i] = d;
    atomicAdd(&g_cnt[d], 1);
}

// ---------------- K3: scan stage A — per-block sums ----------------
__global__ void scanA_kernel() {
    __shared__ int sr[1024];
    int t = threadIdx.x;
    int i = blockIdx.x * 1024 + t;
    sr[t] = (i < NN) ? g_cnt[i] : 0;
    __syncthreads();
#pragma unroll
    for (int s = 512; s > 0; s >>= 1) {
        if (t < s) sr[t] += sr[t + s];
        __syncthreads();
    }
    if (t == 0) g_bsum[blockIdx.x] = sr[0];
}

// ---------------- K4: scan stage B — serial scan of block sums ----------------
__global__ void scanB_kernel() {
    if (threadIdx.x == 0) {
        int run = 0;
#pragma unroll 2
        for (int b = 0; b < SCAN_BLOCKS; b++) {
            g_boff[b] = run;
            run += g_bsum[b];
        }
    }
}

// ---------------- K5: scan stage C — write row offsets ----------------
__global__ void scanC_kernel() {
    __shared__ int sc[1024];
    int t = threadIdx.x;
    int i = blockIdx.x * 1024 + t;
    int v = (i < NN) ? g_cnt[i] : 0;
    sc[t] = v;
    __syncthreads();
#pragma unroll
    for (int off = 1; off < 1024; off <<= 1) {
        int add = (t >= off) ? sc[t - off] : 0;
        __syncthreads();
        sc[t] += add;
        __syncthreads();
    }
    int excl = sc[t] - v + g_boff[blockIdx.x];
    if (i < NN) { g_row[i] = excl; g_pos[i] = excl; }
    if (i == NN) g_row[NN] = excl;
}

// ---------------- K6: scatter src into CSR order ----------------
__global__ void scatter_kernel() {
    int i = blockIdx.x * blockDim.x + threadIdx.x;
    if (i >= EE) return;
    int s = g_src[i], d = g_dst[i];
    int p = atomicAdd(&g_pos[d], 1);
    g_esrc[p] = s;
}

// ---------------- K7: GEMM1 (4 nodes x 8 cols / thread, k-chunk 32) ----------
#define G_NODES 256
#define G_KC    32
#define G_SMEM  ((256 * 32 + G_NODES * (G_KC + 1)) * sizeof(float))

__global__ void __launch_bounds__(256, 3)
gemm1_kernel(const float* __restrict__ x,
             const float* __restrict__ W1l,
             const float* __restrict__ W1r) {
    extern __shared__ float smem[];
    float* Ws = smem;                 // [256 k][32 c]
    float* xs = smem + 256 * 32;      // [256 node][33]

    int t = threadIdx.x;
    for (int i = t; i < 256 * 16; i += 256) {
        int k = i >> 4, c = i & 15;
        Ws[k * 32 + c]      = W1l[i];
        Ws[k * 32 + 16 + c] = W1r[i];
    }

    int nodeBase = blockIdx.x * G_NODES;
    int cg = (t & 3) * 8;
    int ng = (t >> 2) * 4;

    float acc[4][8];
#pragma unroll
    for (int m = 0; m < 4; m++)
#pragma unroll
        for (int c = 0; c < 8; c++) acc[m][c] = 0.0f;

    for (int kc = 0; kc < 256; kc += G_KC) {
        __syncthreads();
        // 256 nodes x 32 k = 2048 float4; 8 iters, 8 threads per node row.
#pragma unroll
        for (int it = 0; it < 8; it++) {
            int idx = t + 256 * it;
            int node = idx >> 3;
            int k4 = (idx & 7) * 4;
            int gnode = nodeBase + node;
            float4 v = (gnode < NN)
                ? *(const float4*)(x + (size_t)gnode * 256 + kc + k4)
                : make_float4(0.f, 0.f, 0.f, 0.f);
            float* p = xs + node * (G_KC + 1) + k4;
            p[0] = v.x; p[1] = v.y; p[2] = v.z; p[3] = v.w;
        }
        __syncthreads();

#pragma unroll 4
        for (int k = 0; k < G_KC; k++) {
            float w[8];
            *(float4*)&w[0] = *(const float4*)&Ws[(kc + k) * 32 + cg];
            *(float4*)&w[4] = *(const float4*)&Ws[(kc + k) * 32 + cg + 4];
            float xm[4];
#pragma unroll
            for (int m = 0; m < 4; m++) xm[m] = xs[(ng + m) * (G_KC + 1) + k];
#pragma unroll
            for (int m = 0; m < 4; m++)
#pragma unroll
                for (int c = 0; c < 8; c++)
                    acc[m][c] = fmaf(xm[m], w[c], acc[m][c]);
        }
    }

#pragma unroll
    for (int m = 0; m < 4; m++) {
        int node = nodeBase + ng + m;
        if (node < NN) {
            float* dstp = (cg < 16) ? (g_xl1 + node * 16 + cg)
                                    : (g_xr1 + node * 16 + (cg - 16));
            *(float4*)(dstp)     = make_float4(acc[m][0], acc[m][1], acc[m][2], acc[m][3]);
            *(float4*)(dstp + 4) = make_float4(acc[m][4], acc[m][5], acc[m][6], acc[m][7]);
        }
    }
}

// ---------------- K8: edge pass layer 1 — warp per dst node ----------------
// 16 lanes per edge (one per channel), 2 edges per warp-iteration.
// No atomics: den/agg accumulate in registers, normalized store at end.
__global__ void edge1_csr_kernel(const float* __restrict__ a1) {
    int warp = (blockIdx.x * blockDim.x + threadIdx.x) >> 5;
    if (warp >= NN) return;
    int lane = threadIdx.x & 31;
    int c = lane & 15;
    int half = lane >> 4;
    unsigned hmask = 0xFFFFu << (half * 16);

    int d = warp;
    int beg = g_row[d], end = g_row[d + 1];

    float xr_c = g_xr1[d * 16 + c];
    float a_c = __ldg(a1 + c);

    float acc = 0.0f, den = 0.0f;
    for (int i = beg + half; i < end; i += 2) {
        int s = g_esrc[i];
        float xl = g_xl1[s * 16 + c];
        float t = lrelu02(xl + xr_c) * a_c;
        t += __shfl_xor_sync(hmask, t, 1);
        t += __shfl_xor_sync(hmask, t, 2);
        float ex = __expf(t);
        den += ex;
        acc = fmaf(ex, xl, acc);
    }
    acc += __shfl_xor_sync(0xFFFFFFFFu, acc, 16);
    den += __shfl_xor_sync(0xFFFFFFFFu, den, 16);
    if (half == 0)
        g_agg1[d * 16 + c] = acc / (den + 1e-16f);
}

// ---------------- K9: node layer-2: bias + elu + tiny GEMM ----------------
__global__ void node2_kernel(const float* __restrict__ b1,
                             const float* __restrict__ W2l,
                             const float* __restrict__ W2r) {
    __shared__ float sWl[128], sWr[128], sb1[16];
    int t = threadIdx.x;
    if (t < 128) { sWl[t] = W2l[t]; sWr[t] = W2r[t]; }
    if (t < 16)  { sb1[t] = b1[t]; }
    __syncthreads();

    int n = blockIdx.x * blockDim.x + t;
    if (n >= NN) return;

    float v[16];
    const float4* ap = (const float4*)(g_agg1 + n * 16);
#pragma unroll
    for (int h = 0; h < 4; h++) {
        float4 a = ap[h];
        float t0 = a.x + sb1[h * 4 + 0];
        float t1 = a.y + sb1[h * 4 + 1];
        float t2 = a.z + sb1[h * 4 + 2];
        float t3 = a.w + sb1[h * 4 + 3];
        v[h * 4 + 0] = (t0 > 0.0f) ? t0 : (__expf(t0) - 1.0f);
        v[h * 4 + 1] = (t1 > 0.0f) ? t1 : (__expf(t1) - 1.0f);
        v[h * 4 + 2] = (t2 > 0.0f) ? t2 : (__expf(t2) - 1.0f);
        v[h * 4 + 3] = (t3 > 0.0f) ? t3 : (__expf(t3) - 1.0f);
    }

    float ol[8], orr[8];
#pragma unroll
    for (int c = 0; c < 8; c++) { ol[c] = 0.0f; orr[c] = 0.0f; }
#pragma unroll
    for (int k = 0; k < 16; k++) {
#pragma unroll
        for (int c = 0; c < 8; c++) {
            ol[c]  = fmaf(v[k], sWl[k * 8 + c], ol[c]);
            orr[c] = fmaf(v[k], sWr[k * 8 + c], orr[c]);
        }
    }
    float4* pl = (float4*)(g_xl2 + n * 8);
    float4* pr = (float4*)(g_xr2 + n * 8);
    pl[0] = make_float4(ol[0], ol[1], ol[2], ol[3]);
    pl[1] = make_float4(ol[4], ol[5], ol[6], ol[7]);
    pr[0] = make_float4(orr[0], orr[1], orr[2], orr[3]);
    pr[1] = make_float4(orr[4], orr[5], orr[6], orr[7]);
}

// ---------------- K10: edge pass layer 2 — warp per dst node, fused output --
// 8 lanes per edge, 4 edges per warp-iteration. Writes sigmoid directly.
__global__ void edge2_csr_kernel(const float* __restrict__ a2,
                                 const float* __restrict__ b2,
                                 float* __restrict__ out) {
    int warp = (blockIdx.x * blockDim.x + threadIdx.x) >> 5;
    if (warp >= NN) return;
    int lane = threadIdx.x & 31;
    int c = lane & 7;
    int quarter = lane >> 3;
    unsigned qmask = 0xFFu << (quarter * 8);

    int d = warp;
    int beg = g_row[d], end = g_row[d + 1];

    float xr_c = g_xr2[d * 8 + c];
    float a_c = __ldg(a2 + c);

    float acc = 0.0f, den = 0.0f;
    for (int i = beg + quarter; i < end; i += 4) {
        int s = g_esrc[i];
        float xl = g_xl2[s * 8 + c];
        float t = lrelu02(xl + xr_c) * a_c;
        t += __shfl_xor_sync(qmask, t, 1);
        t += __shfl_xor_sync(qmask, t, 2);
        t += __shfl_xor_sync(qmask, t, 4);
        float ex = __expf(t);
        den += ex;
        acc = fmaf(ex, xl, acc);
    }
    acc += __shfl_xor_sync(0xFFFFFFFFu, acc, 8);
    den += __shfl_xor_sync(0xFFFFFFFFu, den, 8);
    acc += __shfl_xor_sync(0xFFFFFFFFu, acc, 16);
    den += __shfl_xor_sync(0xFFFFFFFFu, den, 16);

    if (lane < 8) {
        float v = acc / (den + 1e-16f) + __ldg(b2 + c);
        out[d * 8 + c] = 1.0f / (1.0f + __expf(-v));
    }
}

// ---------------- launch ----------------
extern "C" void kernel_launch(void* const* d_in, const int* in_sizes, int n_in,
                              void* d_out, int out_size) {
    const float* x   = (const float*)d_in[0];
    const void*  ei  = d_in[1];
    const float* W1l = (const float*)d_in[2];
    const float* W1r = (const float*)d_in[3];
    const float* a1  = (const float*)d_in[4];
    const float* b1  = (const float*)d_in[5];
    const float* W2l = (const float*)d_in[6];
    const float* W2r = (const float*)d_in[7];
    const float* a2  = (const float*)d_in[8];
    const float* b2  = (const float*)d_in[9];
    float* out = (float*)d_out;

    static bool configured = false;
    if (!configured) {
        cudaFuncSetAttribute(gemm1_kernel,
                             cudaFuncAttributeMaxDynamicSharedMemorySize,
                             (int)G_SMEM);
        configured = true;
    }

    const int EB = (EE + 255) / 256;
    const int NWB = (NN * 32 + 255) / 256;   // warp-per-node grids

    detect_kernel<<<1, 256>>>((const long long*)ei);
    zero_cnt_kernel<<<SCAN_BLOCKS, 1024>>>();
    convert_hist_kernel<<<EB, 256>>>(ei);
    scanA_kernel<<<SCAN_BLOCKS, 1024>>>();
    scanB_kernel<<<1, 32>>>();
    scanC_kernel<<<SCAN_BLOCKS, 1024>>>();
    scatter_kernel<<<EB, 256>>>();
    gemm1_kernel<<<(NN + G_NODES - 1) / G_NODES, 256, G_SMEM>>>(x, W1l, W1r);
    edge1_csr_kernel<<<NWB, 256>>>(a1);
    node2_kernel<<<(NN + 255) / 256, 256>>>(b1, W2l, W2r);
    edge2_csr_kernel<<<NWB, 256>>>(a2, b2, out);
}

// round 4
// speedup vs baseline: 2.0799x; 1.0155x over previous
#include <cuda_runtime.h>
#include <cuda_bf16.h>

#define NN 100000
#define EE 3200000
#define SCAN_BLOCKS 98   // ceil(NN/1024)

// ---------------- scratch (device globals; no allocations) ----------------
__device__ int   g_src[EE];
__device__ int   g_dst[EE];
__device__ int   g_esrc[EE];        // src sorted by dst (CSR)
__device__ int   g_cnt[NN];
__device__ int   g_row[NN + 1];
__device__ int   g_pos[NN];
__device__ int   g_bsum[SCAN_BLOCKS];
__device__ int   g_boff[SCAN_BLOCKS];
__device__ float g_xl1[NN * 16];
__device__ float g_xr1[NN * 16];
__device__ float g_agg1[NN * 16];   // normalized attention output, layer 1
__device__ float g_xl2[NN * 8];
__device__ float g_xr2[NN * 8];
__device__ int   g_is64;

// ---------------- helpers ----------------
__device__ __forceinline__ float lrelu02(float x) {
    return fmaxf(x, 0.2f * x);
}

__device__ __forceinline__ void fma2(float2& d, float2 a, float2 b, float2 c) {
    asm("fma.rn.f32x2 %0, %1, %2, %3;"
        : "=l"(reinterpret_cast<unsigned long long&>(d))
        : "l"(reinterpret_cast<unsigned long long&>(a)),
          "l"(reinterpret_cast<unsigned long long&>(b)),
          "l"(reinterpret_cast<unsigned long long&>(c)));
}

// ---------------- K1: zero histogram + detect dtype (block 0) ----------------
__global__ void zero_detect_kernel(const long long* __restrict__ ei) {
    int i = blockIdx.x * blockDim.x + threadIdx.x;
    if (i < NN) g_cnt[i] = 0;
    if (blockIdx.x == 0) {
        int bad = 0;
        for (int j = threadIdx.x; j < 2048; j += 1024) {
            long long v = ei[j];
            if (v < 0 || v >= (long long)NN) bad = 1;
        }
        bad = __syncthreads_or(bad);
        if (threadIdx.x == 0) g_is64 = bad ? 0 : 1;
    }
}

// ---------------- K2: convert edge_index -> int32 + histogram ----------------
__global__ void convert_hist_kernel(const void* __restrict__ ei) {
    int i = blockIdx.x * blockDim.x + threadIdx.x;
    if (i >= EE) return;
    int s, d;
    if (g_is64) {
        const long long* p = (const long long*)ei;
        s = (int)p[i];
        d = (int)p[EE + i];
    } else {
        const int* p = (const int*)ei;
        s = p[i];
        d = p[EE + i];
    }
    g_src[i] = s;
    g_dst[i] = d;
    atomicAdd(&g_cnt[d], 1);
}

// ---------------- K3: scan stage A — per-block sums ----------------
__global__ void scanA_kernel() {
    __shared__ int sr[1024];
    int t = threadIdx.x;
    int i = blockIdx.x * 1024 + t;
    sr[t] = (i < NN) ? g_cnt[i] : 0;
    __syncthreads();
#pragma unroll
    for (int s = 512; s > 0; s >>= 1) {
        if (t < s) sr[t] += sr[t + s];
        __syncthreads();
    }
    if (t == 0) g_bsum[blockIdx.x] = sr[0];
}

// ---------------- K4: scan stage B — serial scan of block sums ----------------
__global__ void scanB_kernel() {
    if (threadIdx.x == 0) {
        int run = 0;
#pragma unroll 2
        for (int b = 0; b < SCAN_BLOCKS; b++) {
            g_boff[b] = run;
            run += g_bsum[b];
        }
    }
}

// ---------------- K5: scan stage C — write row offsets ----------------
__global__ void scanC_kernel() {
    __shared__ int sc[1024];
    int t = threadIdx.x;
    int i = blockIdx.x * 1024 + t;
    int v = (i < NN) ? g_cnt[i] : 0;
    sc[t] = v;
    __syncthreads();
#pragma unroll
    for (int off = 1; off < 1024; off <<= 1) {
        int add = (t >= off) ? sc[t - off] : 0;
        __syncthreads();
        sc[t] += add;
        __syncthreads();
    }
    int excl = sc[t] - v + g_boff[blockIdx.x];
    if (i < NN) { g_row[i] = excl; g_pos[i] = excl; }
    if (i == NN) g_row[NN] = excl;
}

// ---------------- K6: scatter src into CSR order ----------------
__global__ void scatter_kernel() {
    int i = blockIdx.x * blockDim.x + threadIdx.x;
    if (i >= EE) return;
    int s = g_src[i], d = g_dst[i];
    int p = atomicAdd(&g_pos[d], 1);
    g_esrc[p] = s;
}

// ---------------- K7: GEMM1 — f32x2 packed FMA ----------------
// 512-node tile, 256 threads. Thread owns 4 nodes x 16 cols (one W half).
// t&1: 0 -> cols 0-15 (W1l), 1 -> cols 16-31 (W1r). acc as 8 float2 per node.
#define G_NODES 512
#define G_KC    16
#define G_XS    (G_KC + 1)
#define G_SMEM  ((256 * 32 + G_NODES * G_XS) * sizeof(float))

__global__ void __launch_bounds__(256, 2)
gemm1_kernel(const float* __restrict__ x,
             const float* __restrict__ W1l,
             const float* __restrict__ W1r) {
    extern __shared__ float smem[];
    float* Ws = smem;                 // [256 k][32 c]
    float* xs = smem + 256 * 32;      // [512 node][G_XS]

    int t = threadIdx.x;
    // Weights: cols 0-15 = W1l, 16-31 = W1r
    for (int i = t; i < 256 * 16; i += 256) {
        int k = i >> 4, c = i & 15;
        Ws[k * 32 + c]      = W1l[i];
        Ws[k * 32 + 16 + c] = W1r[i];
    }

    int nodeBase = blockIdx.x * G_NODES;
    int half = t & 1;            // which 16-col half
    int ng = (t >> 1) * 4;       // node base within tile

    float2 acc[4][8];
#pragma unroll
    for (int m = 0; m < 4; m++)
#pragma unroll
        for (int j = 0; j < 8; j++) acc[m][j] = make_float2(0.f, 0.f);

    for (int kc = 0; kc < 256; kc += G_KC) {
        __syncthreads();
        // Load 512 nodes x 16 k = 2048 float4, 8 iters.
#pragma unroll
        for (int it = 0; it < 8; it++) {
            int idx = t + 256 * it;
            int node = idx >> 2;
            int k4 = (idx & 3) * 4;
            int gnode = nodeBase + node;
            float4 v = (gnode < NN)
                ? *(const float4*)(x + (size_t)gnode * 256 + kc + k4)
                : make_float4(0.f, 0.f, 0.f, 0.f);
            float* p = xs + node * G_XS + k4;
            p[0] = v.x; p[1] = v.y; p[2] = v.z; p[3] = v.w;
        }
        __syncthreads();

#pragma unroll
        for (int k = 0; k < G_KC; k++) {
            const float4* wp = (const float4*)&Ws[(kc + k) * 32 + half * 16];
            float4 w0 = wp[0], w1 = wp[1], w2 = wp[2], w3 = wp[3];
            float2 w[8];
            w[0] = make_float2(w0.x, w0.y); w[1] = make_float2(w0.z, w0.w);
            w[2] = make_float2(w1.x, w1.y); w[3] = make_float2(w1.z, w1.w);
            w[4] = make_float2(w2.x, w2.y); w[5] = make_float2(w2.z, w2.w);
            w[6] = make_float2(w3.x, w3.y); w[7] = make_float2(w3.z, w3.w);
#pragma unroll
            for (int m = 0; m < 4; m++) {
                float xm = xs[(ng + m) * G_XS + k];
                float2 xp = make_float2(xm, xm);
#pragma unroll
                for (int j = 0; j < 8; j++)
                    fma2(acc[m][j], xp, w[j], acc[m][j]);
            }
        }
    }

    float* base = half ? g_xr1 : g_xl1;
#pragma unroll
    for (int m = 0; m < 4; m++) {
        int node = nodeBase + ng + m;
        if (node < NN) {
            float* dstp = base + node * 16;
            *(float4*)(dstp + 0)  = make_float4(acc[m][0].x, acc[m][0].y, acc[m][1].x, acc[m][1].y);
            *(float4*)(dstp + 4)  = make_float4(acc[m][2].x, acc[m][2].y, acc[m][3].x, acc[m][3].y);
            *(float4*)(dstp + 8)  = make_float4(acc[m][4].x, acc[m][4].y, acc[m][5].x, acc[m][5].y);
            *(float4*)(dstp + 12) = make_float4(acc[m][6].x, acc[m][6].y, acc[m][7].x, acc[m][7].y);
        }
    }
}

// ---------------- K8: edge pass layer 1 — warp per dst node, unroll 2 --------
__global__ void edge1_csr_kernel(const float* __restrict__ a1) {
    int warp = (blockIdx.x * blockDim.x + threadIdx.x) >> 5;
    if (warp >= NN) return;
    int lane = threadIdx.x & 31;
    int c = lane & 15;
    int half = lane >> 4;
    unsigned hmask = 0xFFFFu << (half * 16);

    int d = warp;
    int beg = g_row[d], end = g_row[d + 1];

    float xr_c = g_xr1[d * 16 + c];
    float a_c = __ldg(a1 + c);

    float acc = 0.0f, den = 0.0f;
    int i = beg + half;
    for (; i + 2 < end; i += 4) {
        int s0 = g_esrc[i];
        int s1 = g_esrc[i + 2];
        float xl0 = g_xl1[s0 * 16 + c];
        float xl1v = g_xl1[s1 * 16 + c];
        float t0 = lrelu02(xl0 + xr_c) * a_c;
        float t1 = lrelu02(xl1v + xr_c) * a_c;
        t0 += __shfl_xor_sync(hmask, t0, 1);
        t1 += __shfl_xor_sync(hmask, t1, 1);
        t0 += __shfl_xor_sync(hmask, t0, 2);
        t1 += __shfl_xor_sync(hmask, t1, 2);
        float e0 = __expf(t0);
        float e1 = __expf(t1);
        den += e0 + e1;
        acc = fmaf(e0, xl0, acc);
        acc = fmaf(e1, xl1v, acc);
    }
    if (i < end) {
        int s = g_esrc[i];
        float xl = g_xl1[s * 16 + c];
        float tt = lrelu02(xl + xr_c) * a_c;
        tt += __shfl_xor_sync(hmask, tt, 1);
        tt += __shfl_xor_sync(hmask, tt, 2);
        float ex = __expf(tt);
        den += ex;
        acc = fmaf(ex, xl, acc);
    }
    acc += __shfl_xor_sync(0xFFFFFFFFu, acc, 16);
    den += __shfl_xor_sync(0xFFFFFFFFu, den, 16);
    if (half == 0)
        g_agg1[d * 16 + c] = acc / (den + 1e-16f);
}

// ---------------- K9: node layer-2: bias + elu + tiny GEMM ----------------
__global__ void node2_kernel(const float* __restrict__ b1,
                             const float* __restrict__ W2l,
                             const float* __restrict__ W2r) {
    __shared__ float sWl[128], sWr[128], sb1[16];
    int t = threadIdx.x;
    if (t < 128) { sWl[t] = W2l[t]; sWr[t] = W2r[t]; }
    if (t < 16)  { sb1[t] = b1[t]; }
    __syncthreads();

    int n = blockIdx.x * blockDim.x + t;
    if (n >= NN) return;

    float v[16];
    const float4* ap = (const float4*)(g_agg1 + n * 16);
#pragma unroll
    for (int h = 0; h < 4; h++) {
        float4 a = ap[h];
        float t0 = a.x + sb1[h * 4 + 0];
        float t1 = a.y + sb1[h * 4 + 1];
        float t2 = a.z + sb1[h * 4 + 2];
        float t3 = a.w + sb1[h * 4 + 3];
        v[h * 4 + 0] = (t0 > 0.0f) ? t0 : (__expf(t0) - 1.0f);
        v[h * 4 + 1] = (t1 > 0.0f) ? t1 : (__expf(t1) - 1.0f);
        v[h * 4 + 2] = (t2 > 0.0f) ? t2 : (__expf(t2) - 1.0f);
        v[h * 4 + 3] = (t3 > 0.0f) ? t3 : (__expf(t3) - 1.0f);
    }

    float ol[8], orr[8];
#pragma unroll
    for (int cc = 0; cc < 8; cc++) { ol[cc] = 0.0f; orr[cc] = 0.0f; }
#pragma unroll
    for (int k = 0; k < 16; k++) {
#pragma unroll
        for (int cc = 0; cc < 8; cc++) {
            ol[cc]  = fmaf(v[k], sWl[k * 8 + cc], ol[cc]);
            orr[cc] = fmaf(v[k], sWr[k * 8 + cc], orr[cc]);
        }
    }
    float4* pl = (float4*)(g_xl2 + n * 8);
    float4* pr = (float4*)(g_xr2 + n * 8);
    pl[0] = make_float4(ol[0], ol[1], ol[2], ol[3]);
    pl[1] = make_float4(ol[4], ol[5], ol[6], ol[7]);
    pr[0] = make_float4(orr[0], orr[1], orr[2], orr[3]);
    pr[1] = make_float4(orr[4], orr[5], orr[6], orr[7]);
}

// ---------------- K10: edge pass layer 2 — warp per dst node, unroll 2 -------
__global__ void edge2_csr_kernel(const float* __restrict__ a2,
                                 const float* __restrict__ b2,
                                 float* __restrict__ out) {
    int warp = (blockIdx.x * blockDim.x + threadIdx.x) >> 5;
    if (warp >= NN) return;
    int lane = threadIdx.x & 31;
    int c = lane & 7;
    int quarter = lane >> 3;
    unsigned qmask = 0xFFu << (quarter * 8);

    int d = warp;
    int beg = g_row[d], end = g_row[d + 1];

    float xr_c = g_xr2[d * 8 + c];
    float a_c = __ldg(a2 + c);

    float acc = 0.0f, den = 0.0f;
    int i = beg + quarter;
    for (; i + 4 < end; i += 8) {
        int s0 = g_esrc[i];
        int s1 = g_esrc[i + 4];
        float xl0 = g_xl2[s0 * 8 + c];
        float xl1v = g_xl2[s1 * 8 + c];
        float t0 = lrelu02(xl0 + xr_c) * a_c;
        float t1 = lrelu02(xl1v + xr_c) * a_c;
        t0 += __shfl_xor_sync(qmask, t0, 1);
        t1 += __shfl_xor_sync(qmask, t1, 1);
        t0 += __shfl_xor_sync(qmask, t0, 2);
        t1 += __shfl_xor_sync(qmask, t1, 2);
        t0 += __shfl_xor_sync(qmask, t0, 4);
        t1 += __shfl_xor_sync(qmask, t1, 4);
        float e0 = __expf(t0);
        float e1 = __expf(t1);
        den += e0 + e1;
        acc = fmaf(e0, xl0, acc);
        acc = fmaf(e1, xl1v, acc);
    }
    if (i < end) {
        int s = g_esrc[i];
        float xl = g_xl2[s * 8 + c];
        float tt = lrelu02(xl + xr_c) * a_c;
        tt += __shfl_xor_sync(qmask, tt, 1);
        tt += __shfl_xor_sync(qmask, tt, 2);
        tt += __shfl_xor_sync(qmask, tt, 4);
        float ex = __expf(tt);
        den += ex;
        acc = fmaf(ex, xl, acc);
    }
    acc += __shfl_xor_sync(0xFFFFFFFFu, acc, 8);
    den += __shfl_xor_sync(0xFFFFFFFFu, den, 8);
    acc += __shfl_xor_sync(0xFFFFFFFFu, acc, 16);
    den += __shfl_xor_sync(0xFFFFFFFFu, den, 16);

    if (lane < 8) {
        float v = acc / (den + 1e-16f) + __ldg(b2 + c);
        out[d * 8 + c] = 1.0f / (1.0f + __expf(-v));
    }
}

// ---------------- launch ----------------
extern "C" void kernel_launch(void* const* d_in, const int* in_sizes, int n_in,
                              void* d_out, int out_size) {
    const float* x   = (const float*)d_in[0];
    const void*  ei  = d_in[1];
    const float* W1l = (const float*)d_in[2];
    const float* W1r = (const float*)d_in[3];
    const float* a1  = (const float*)d_in[4];
    const float* b1  = (const float*)d_in[5];
    const float* W2l = (const float*)d_in[6];
    const float* W2r = (const float*)d_in[7];
    const float* a2  = (const float*)d_in[8];
    const float* b2  = (const float*)d_in[9];
    float* out = (float*)d_out;

    static bool configured = false;
    if (!configured) {
        cudaFuncSetAttribute(gemm1_kernel,
                             cudaFuncAttributeMaxDynamicSharedMemorySize,
                             (int)G_SMEM);
        configured = true;
    }

    const int EB = (EE + 255) / 256;
    const int NWB = (NN * 32 + 255) / 256;   // warp-per-node grids

    zero_detect_kernel<<<SCAN_BLOCKS, 1024>>>((const long long*)ei);
    convert_hist_kernel<<<EB, 256>>>(ei);
    scanA_kernel<<<SCAN_BLOCKS, 1024>>>();
    scanB_kernel<<<1, 32>>>();
    scanC_kernel<<<SCAN_BLOCKS, 1024>>>();
    scatter_kernel<<<EB, 256>>>();
    gemm1_kernel<<<(NN + G_NODES - 1) / G_NODES, 256, G_SMEM>>>(x, W1l, W1r);
    edge1_csr_kernel<<<NWB, 256>>>(a1);
    node2_kernel<<<(NN + 255) / 256, 256>>>(b1, W2l, W2r);
    edge2_csr_kernel<<<NWB, 256>>>(a2, b2, out);
}

// round 5
// speedup vs baseline: 2.2052x; 1.0603x over previous
#include <cuda_runtime.h>
#include <cuda_bf16.h>

#define NN 100000
#define EE 3200000
#define K_SLOT 80
#define SPILL_MAX 65536

// ---------------- scratch (device globals; no allocations) ----------------
__device__ int   g_esrc2[NN * K_SLOT];   // bucketed src per dst (fixed stride)
__device__ int   g_cnt[NN];
__device__ int   g_spill_s[SPILL_MAX];
__device__ int   g_spill_d[SPILL_MAX];
__device__ int   g_spill_cnt;
__device__ float g_xl1[NN * 16];
__device__ float g_xr1[NN * 16];
__device__ float g_xl2[NN * 8];
__device__ float g_xr2[NN * 8];
__device__ int   g_is64;

// ---------------- helpers ----------------
__device__ __forceinline__ float lrelu02(float x) {
    return fmaxf(x, 0.2f * x);
}

__device__ __forceinline__ void fma2(float2& d, float2 a, float2 b, float2 c) {
    asm("fma.rn.f32x2 %0, %1, %2, %3;"
        : "=l"(reinterpret_cast<unsigned long long&>(d))
        : "l"(reinterpret_cast<unsigned long long&>(a)),
          "l"(reinterpret_cast<unsigned long long&>(b)),
          "l"(reinterpret_cast<unsigned long long&>(c)));
}

// ---------------- K1: zero counters + detect dtype ----------------
__global__ void init_kernel(const long long* __restrict__ ei) {
    int i = blockIdx.x * blockDim.x + threadIdx.x;
    if (i < NN) g_cnt[i] = 0;
    if (blockIdx.x == 0) {
        if (threadIdx.x == 0) g_spill_cnt = 0;
        int bad = 0;
        for (int j = threadIdx.x; j < 2048; j += 1024) {
            long long v = ei[j];
            if (v < 0 || v >= (long long)NN) bad = 1;
        }
        bad = __syncthreads_or(bad);
        if (threadIdx.x == 0) g_is64 = bad ? 0 : 1;
    }
}

// ---------------- K2: single-pass bucket build ----------------
__global__ void build_kernel(const void* __restrict__ ei) {
    int i = blockIdx.x * blockDim.x + threadIdx.x;
    if (i >= EE) return;
    int s, d;
    if (g_is64) {
        const long long* p = (const long long*)ei;
        s = (int)p[i];
        d = (int)p[EE + i];
    } else {
        const int* p = (const int*)ei;
        s = p[i];
        d = p[EE + i];
    }
    int p = atomicAdd(&g_cnt[d], 1);
    if (p < K_SLOT) {
        g_esrc2[d * K_SLOT + p] = s;
    } else {
        int q = atomicAdd(&g_spill_cnt, 1);
        if (q < SPILL_MAX) { g_spill_s[q] = s; g_spill_d[q] = d; }
    }
}

// ---------------- K3: GEMM1 — f32x2 packed FMA ----------------
#define G_NODES 512
#define G_KC    16
#define G_XS    (G_KC + 1)
#define G_SMEM  ((256 * 32 + G_NODES * G_XS) * sizeof(float))

__global__ void __launch_bounds__(256, 2)
gemm1_kernel(const float* __restrict__ x,
             const float* __restrict__ W1l,
             const float* __restrict__ W1r) {
    extern __shared__ float smem[];
    float* Ws = smem;                 // [256 k][32 c]
    float* xs = smem + 256 * 32;      // [512 node][G_XS]

    int t = threadIdx.x;
    for (int i = t; i < 256 * 16; i += 256) {
        int k = i >> 4, c = i & 15;
        Ws[k * 32 + c]      = W1l[i];
        Ws[k * 32 + 16 + c] = W1r[i];
    }

    int nodeBase = blockIdx.x * G_NODES;
    int half = t & 1;
    int ng = (t >> 1) * 4;

    float2 acc[4][8];
#pragma unroll
    for (int m = 0; m < 4; m++)
#pragma unroll
        for (int j = 0; j < 8; j++) acc[m][j] = make_float2(0.f, 0.f);

    for (int kc = 0; kc < 256; kc += G_KC) {
        __syncthreads();
#pragma unroll
        for (int it = 0; it < 8; it++) {
            int idx = t + 256 * it;
            int node = idx >> 2;
            int k4 = (idx & 3) * 4;
            int gnode = nodeBase + node;
            float4 v = (gnode < NN)
                ? *(const float4*)(x + (size_t)gnode * 256 + kc + k4)
                : make_float4(0.f, 0.f, 0.f, 0.f);
            float* p = xs + node * G_XS + k4;
            p[0] = v.x; p[1] = v.y; p[2] = v.z; p[3] = v.w;
        }
        __syncthreads();

#pragma unroll
        for (int k = 0; k < G_KC; k++) {
            const float4* wp = (const float4*)&Ws[(kc + k) * 32 + half * 16];
            float4 w0 = wp[0], w1 = wp[1], w2 = wp[2], w3 = wp[3];
            float2 w[8];
            w[0] = make_float2(w0.x, w0.y); w[1] = make_float2(w0.z, w0.w);
            w[2] = make_float2(w1.x, w1.y); w[3] = make_float2(w1.z, w1.w);
            w[4] = make_float2(w2.x, w2.y); w[5] = make_float2(w2.z, w2.w);
            w[6] = make_float2(w3.x, w3.y); w[7] = make_float2(w3.z, w3.w);
#pragma unroll
            for (int m = 0; m < 4; m++) {
                float xm = xs[(ng + m) * G_XS + k];
                float2 xp = make_float2(xm, xm);
#pragma unroll
                for (int j = 0; j < 8; j++)
                    fma2(acc[m][j], xp, w[j], acc[m][j]);
            }
        }
    }

    float* base = half ? g_xr1 : g_xl1;
#pragma unroll
    for (int m = 0; m < 4; m++) {
        int node = nodeBase + ng + m;
        if (node < NN) {
            float* dstp = base + node * 16;
            *(float4*)(dstp + 0)  = make_float4(acc[m][0].x, acc[m][0].y, acc[m][1].x, acc[m][1].y);
            *(float4*)(dstp + 4)  = make_float4(acc[m][2].x, acc[m][2].y, acc[m][3].x, acc[m][3].y);
            *(float4*)(dstp + 8)  = make_float4(acc[m][4].x, acc[m][4].y, acc[m][5].x, acc[m][5].y);
            *(float4*)(dstp + 12) = make_float4(acc[m][6].x, acc[m][6].y, acc[m][7].x, acc[m][7].y);
        }
    }
}

// ---------------- K4: edge layer 1 + fused node2 ----------------
// Warp per dst node; 16 lanes per edge, 2 edges in flight per half, unroll 2.
// Epilogue: normalize, bias+ELU, 16->8|8 transform via shfl, write xl2/xr2.
__global__ void edge1_kernel(const float* __restrict__ a1,
                             const float* __restrict__ b1,
                             const float* __restrict__ W2l,
                             const float* __restrict__ W2r) {
    int warp = (blockIdx.x * blockDim.x + threadIdx.x) >> 5;
    if (warp >= NN) return;
    int lane = threadIdx.x & 31;
    int c = lane & 15;
    int half = lane >> 4;
    unsigned hmask = 0xFFFFu << (half * 16);

    // preload layer-2 weights for this lane's output column
    float w2[16];
#pragma unroll
    for (int k = 0; k < 16; k++) {
        if (lane < 8)       w2[k] = __ldg(W2l + k * 8 + lane);
        else if (lane < 16) w2[k] = __ldg(W2r + k * 8 + (lane - 8));
        else                w2[k] = 0.0f;
    }

    int d = warp;
    int cnt = g_cnt[d];
    int len = cnt < K_SLOT ? cnt : K_SLOT;
    const int* ep = g_esrc2 + d * K_SLOT;

    float xr_c = g_xr1[d * 16 + c];
    float a_c = __ldg(a1 + c);

    float acc = 0.0f, den = 0.0f;
    int j = half;
    for (; j + 2 < len; j += 4) {
        int s0 = ep[j];
        int s1 = ep[j + 2];
        float xl0 = g_xl1[s0 * 16 + c];
        float xl1v = g_xl1[s1 * 16 + c];
        float t0 = lrelu02(xl0 + xr_c) * a_c;
        float t1 = lrelu02(xl1v + xr_c) * a_c;
        t0 += __shfl_xor_sync(hmask, t0, 1);
        t1 += __shfl_xor_sync(hmask, t1, 1);
        t0 += __shfl_xor_sync(hmask, t0, 2);
        t1 += __shfl_xor_sync(hmask, t1, 2);
        float e0 = __expf(t0);
        float e1 = __expf(t1);
        den += e0 + e1;
        acc = fmaf(e0, xl0, acc);
        acc = fmaf(e1, xl1v, acc);
    }
    if (j < len) {
        int s = ep[j];
        float xl = g_xl1[s * 16 + c];
        float tt = lrelu02(xl + xr_c) * a_c;
        tt += __shfl_xor_sync(hmask, tt, 1);
        tt += __shfl_xor_sync(hmask, tt, 2);
        float ex = __expf(tt);
        den += ex;
        acc = fmaf(ex, xl, acc);
    }
    // spill fallback (empty in practice)
    if (cnt > K_SLOT) {
        int ns = g_spill_cnt; if (ns > SPILL_MAX) ns = SPILL_MAX;
        for (int q = 0; q < ns; q++) {
            if (g_spill_d[q] == d) {
                if (half == 0) {
                    int s = g_spill_s[q];
                    float xl = g_xl1[s * 16 + c];
                    float tt = lrelu02(xl + xr_c) * a_c;
                    tt += __shfl_xor_sync(0xFFFFu, tt, 1);
                    tt += __shfl_xor_sync(0xFFFFu, tt, 2);
                    float ex = __expf(tt);
                    den += ex;
                    acc = fmaf(ex, xl, acc);
                }
            }
        }
    }
    acc += __shfl_xor_sync(0xFFFFFFFFu, acc, 16);
    den += __shfl_xor_sync(0xFFFFFFFFu, den, 16);

    // fused node2: bias + elu on half-0 lanes, then 16-wide transform via shfl
    float v = 0.0f;
    if (half == 0) {
        float tt = acc / (den + 1e-16f) + __ldg(b1 + c);
        v = (tt > 0.0f) ? tt : (__expf(tt) - 1.0f);
    }
    float o = 0.0f;
#pragma unroll
    for (int k = 0; k < 16; k++) {
        float vk = __shfl_sync(0xFFFFFFFFu, v, k);
        o = fmaf(vk, w2[k], o);
    }
    if (lane < 8)       g_xl2[d * 8 + lane] = o;
    else if (lane < 16) g_xr2[d * 8 + (lane - 8)] = o;
}

// ---------------- K5: edge layer 2 — warp per dst node, fused output --------
__global__ void edge2_kernel(const float* __restrict__ a2,
                             const float* __restrict__ b2,
                             float* __restrict__ out) {
    int warp = (blockIdx.x * blockDim.x + threadIdx.x) >> 5;
    if (warp >= NN) return;
    int lane = threadIdx.x & 31;
    int c = lane & 7;
    int quarter = lane >> 3;
    unsigned qmask = 0xFFu << (quarter * 8);

    int d = warp;
    int cnt = g_cnt[d];
    int len = cnt < K_SLOT ? cnt : K_SLOT;
    const int* ep = g_esrc2 + d * K_SLOT;

    float xr_c = g_xr2[d * 8 + c];
    float a_c = __ldg(a2 + c);

    float acc = 0.0f, den = 0.0f;
    int j = quarter;
    for (; j + 4 < len; j += 8) {
        int s0 = ep[j];
        int s1 = ep[j + 4];
        float xl0 = g_xl2[s0 * 8 + c];
        float xl1v = g_xl2[s1 * 8 + c];
        float t0 = lrelu02(xl0 + xr_c) * a_c;
        float t1 = lrelu02(xl1v + xr_c) * a_c;
        t0 += __shfl_xor_sync(qmask, t0, 1);
        t1 += __shfl_xor_sync(qmask, t1, 1);
        t0 += __shfl_xor_sync(qmask, t0, 2);
        t1 += __shfl_xor_sync(qmask, t1, 2);
        t0 += __shfl_xor_sync(qmask, t0, 4);
        t1 += __shfl_xor_sync(qmask, t1, 4);
        float e0 = __expf(t0);
        float e1 = __expf(t1);
        den += e0 + e1;
        acc = fmaf(e0, xl0, acc);
        acc = fmaf(e1, xl1v, acc);
    }
    if (j < len) {
        int s = ep[j];
        float xl = g_xl2[s * 8 + c];
        float tt = lrelu02(xl + xr_c) * a_c;
        tt += __shfl_xor_sync(qmask, tt, 1);
        tt += __shfl_xor_sync(qmask, tt, 2);
        tt += __shfl_xor_sync(qmask, tt, 4);
        float ex = __expf(tt);
        den += ex;
        acc = fmaf(ex, xl, acc);
    }
    if (cnt > K_SLOT) {
        int ns = g_spill_cnt; if (ns > SPILL_MAX) ns = SPILL_MAX;
        for (int q = 0; q < ns; q++) {
            if (g_spill_d[q] == d) {
                if (quarter == 0) {
                    int s = g_spill_s[q];
                    float xl = g_xl2[s * 8 + c];
                    float tt = lrelu02(xl + xr_c) * a_c;
                    tt += __shfl_xor_sync(0xFFu, tt, 1);
                    tt += __shfl_xor_sync(0xFFu, tt, 2);
                    tt += __shfl_xor_sync(0xFFu, tt, 4);
                    float ex = __expf(tt);
                    den += ex;
                    acc = fmaf(ex, xl, acc);
                }
            }
        }
    }
    acc += __shfl_xor_sync(0xFFFFFFFFu, acc, 8);
    den += __shfl_xor_sync(0xFFFFFFFFu, den, 8);
    acc += __shfl_xor_sync(0xFFFFFFFFu, acc, 16);
    den += __shfl_xor_sync(0xFFFFFFFFu, den, 16);

    if (lane < 8) {
        float v = acc / (den + 1e-16f) + __ldg(b2 + c);
        out[d * 8 + c] = 1.0f / (1.0f + __expf(-v));
    }
}

// ---------------- launch ----------------
extern "C" void kernel_launch(void* const* d_in, const int* in_sizes, int n_in,
                              void* d_out, int out_size) {
    const float* x   = (const float*)d_in[0];
    const void*  ei  = d_in[1];
    const float* W1l = (const float*)d_in[2];
    const float* W1r = (const float*)d_in[3];
    const float* a1  = (const float*)d_in[4];
    const float* b1  = (const float*)d_in[5];
    const float* W2l = (const float*)d_in[6];
    const float* W2r = (const float*)d_in[7];
    const float* a2  = (const float*)d_in[8];
    const float* b2  = (const float*)d_in[9];
    float* out = (float*)d_out;

    static bool configured = false;
    static cudaStream_t s2;
    static cudaEvent_t evA, evB;
    if (!configured) {
        cudaFuncSetAttribute(gemm1_kernel,
                             cudaFuncAttributeMaxDynamicSharedMemorySize,
                             (int)G_SMEM);
        cudaStreamCreateWithFlags(&s2, cudaStreamNonBlocking);
        cudaEventCreateWithFlags(&evA, cudaEventDisableTiming);
        cudaEventCreateWithFlags(&evB, cudaEventDisableTiming);
        configured = true;
    }

    const int EB = (EE + 255) / 256;
    const int NWB = (NN * 32 + 255) / 256;

    // fork: gemm1 on s2 in parallel with CSR build on default stream
    cudaEventRecord(evA, 0);
    cudaStreamWaitEvent(s2, evA, 0);
    gemm1_kernel<<<(NN + G_NODES - 1) / G_NODES, 256, G_SMEM, s2>>>(x, W1l, W1r);
    cudaEventRecord(evB, s2);

    init_kernel<<<(NN + 1023) / 1024, 1024>>>((const long long*)ei);
    build_kernel<<<EB, 256>>>(ei);

    // join
    cudaStreamWaitEvent(0, evB, 0);
    edge1_kernel<<<NWB, 256>>>(a1, b1, W2l, W2r);
    edge2_kernel<<<NWB, 256>>>(a2, b2, out);
}

// round 6
// speedup vs baseline: 2.3070x; 1.0462x over previous
#include <cuda_runtime.h>
#include <cuda_bf16.h>

#define NN 100000
#define EE 3200000
#define K_SLOT 80
#define SPILL_MAX 65536

// ---------------- scratch (device globals; no allocations) ----------------
__device__ int   g_esrc2[NN * K_SLOT];   // bucketed src per dst (fixed stride)
__device__ int   g_cnt[NN];
__device__ int   g_spill_s[SPILL_MAX];
__device__ int   g_spill_d[SPILL_MAX];
__device__ int   g_spill_cnt;
__device__ float g_xl1[NN * 16];
__device__ float g_xr1[NN * 16];
__device__ float g_xl2[NN * 8];
__device__ float g_xr2[NN * 8];
__device__ int   g_is64;

// ---------------- helpers ----------------
__device__ __forceinline__ float lrelu02(float x) {
    return fmaxf(x, 0.2f * x);
}

__device__ __forceinline__ void fma2(float2& d, float2 a, float2 b, float2 c) {
    asm("fma.rn.f32x2 %0, %1, %2, %3;"
        : "=l"(reinterpret_cast<unsigned long long&>(d))
        : "l"(reinterpret_cast<unsigned long long&>(a)),
          "l"(reinterpret_cast<unsigned long long&>(b)),
          "l"(reinterpret_cast<unsigned long long&>(c)));
}

// ---------------- K1: zero counters + detect dtype ----------------
__global__ void init_kernel(const long long* __restrict__ ei) {
    int i = blockIdx.x * blockDim.x + threadIdx.x;
    if (i < NN) g_cnt[i] = 0;
    if (blockIdx.x == 0) {
        if (threadIdx.x == 0) g_spill_cnt = 0;
        int bad = 0;
        for (int j = threadIdx.x; j < 2048; j += 1024) {
            long long v = ei[j];
            if (v < 0 || v >= (long long)NN) bad = 1;
        }
        bad = __syncthreads_or(bad);
        if (threadIdx.x == 0) g_is64 = bad ? 0 : 1;
    }
}

// ---------------- K2: single-pass bucket build ----------------
__global__ void build_kernel(const void* __restrict__ ei) {
    int i = blockIdx.x * blockDim.x + threadIdx.x;
    if (i >= EE) return;
    int s, d;
    if (g_is64) {
        const long long* p = (const long long*)ei;
        s = (int)p[i];
        d = (int)p[EE + i];
    } else {
        const int* p = (const int*)ei;
        s = p[i];
        d = p[EE + i];
    }
    int p = atomicAdd(&g_cnt[d], 1);
    if (p < K_SLOT) {
        g_esrc2[d * K_SLOT + p] = s;
    } else {
        int q = atomicAdd(&g_spill_cnt, 1);
        if (q < SPILL_MAX) { g_spill_s[q] = s; g_spill_d[q] = d; }
    }
}

// ---------------- K3: GEMM1 — f32x2 packed FMA ----------------
#define G_NODES 512
#define G_KC    16
#define G_XS    (G_KC + 1)
#define G_SMEM  ((256 * 32 + G_NODES * G_XS) * sizeof(float))

__global__ void __launch_bounds__(256, 2)
gemm1_kernel(const float* __restrict__ x,
             const float* __restrict__ W1l,
             const float* __restrict__ W1r) {
    extern __shared__ float smem[];
    float* Ws = smem;                 // [256 k][32 c]
    float* xs = smem + 256 * 32;      // [512 node][G_XS]

    int t = threadIdx.x;
    for (int i = t; i < 256 * 16; i += 256) {
        int k = i >> 4, c = i & 15;
        Ws[k * 32 + c]      = W1l[i];
        Ws[k * 32 + 16 + c] = W1r[i];
    }

    int nodeBase = blockIdx.x * G_NODES;
    int half = t & 1;
    int ng = (t >> 1) * 4;

    float2 acc[4][8];
#pragma unroll
    for (int m = 0; m < 4; m++)
#pragma unroll
        for (int j = 0; j < 8; j++) acc[m][j] = make_float2(0.f, 0.f);

    for (int kc = 0; kc < 256; kc += G_KC) {
        __syncthreads();
#pragma unroll
        for (int it = 0; it < 8; it++) {
            int idx = t + 256 * it;
            int node = idx >> 2;
            int k4 = (idx & 3) * 4;
            int gnode = nodeBase + node;
            float4 v = (gnode < NN)
                ? *(const float4*)(x + (size_t)gnode * 256 + kc + k4)
                : make_float4(0.f, 0.f, 0.f, 0.f);
            float* p = xs + node * G_XS + k4;
            p[0] = v.x; p[1] = v.y; p[2] = v.z; p[3] = v.w;
        }
        __syncthreads();

#pragma unroll
        for (int k = 0; k < G_KC; k++) {
            const float4* wp = (const float4*)&Ws[(kc + k) * 32 + half * 16];
            float4 w0 = wp[0], w1 = wp[1], w2 = wp[2], w3 = wp[3];
            float2 w[8];
            w[0] = make_float2(w0.x, w0.y); w[1] = make_float2(w0.z, w0.w);
            w[2] = make_float2(w1.x, w1.y); w[3] = make_float2(w1.z, w1.w);
            w[4] = make_float2(w2.x, w2.y); w[5] = make_float2(w2.z, w2.w);
            w[6] = make_float2(w3.x, w3.y); w[7] = make_float2(w3.z, w3.w);
#pragma unroll
            for (int m = 0; m < 4; m++) {
                float xm = xs[(ng + m) * G_XS + k];
                float2 xp = make_float2(xm, xm);
#pragma unroll
                for (int j = 0; j < 8; j++)
                    fma2(acc[m][j], xp, w[j], acc[m][j]);
            }
        }
    }

    float* base = half ? g_xr1 : g_xl1;
#pragma unroll
    for (int m = 0; m < 4; m++) {
        int node = nodeBase + ng + m;
        if (node < NN) {
            float* dstp = base + node * 16;
            *(float4*)(dstp + 0)  = make_float4(acc[m][0].x, acc[m][0].y, acc[m][1].x, acc[m][1].y);
            *(float4*)(dstp + 4)  = make_float4(acc[m][2].x, acc[m][2].y, acc[m][3].x, acc[m][3].y);
            *(float4*)(dstp + 8)  = make_float4(acc[m][4].x, acc[m][4].y, acc[m][5].x, acc[m][5].y);
            *(float4*)(dstp + 12) = make_float4(acc[m][6].x, acc[m][6].y, acc[m][7].x, acc[m][7].y);
        }
    }
}

// ---------------- K4: edge layer 1 + fused node2 ----------------
// Warp per dst; 4 lanes per edge (lane = head = float4). 8 edges in flight.
// NO shuffles in the hot loop. Epilogue: reduce, normalize, bias+ELU,
// 16->8|8 transform via shfl, write xl2/xr2.
__global__ void edge1_kernel(const float* __restrict__ a1,
                             const float* __restrict__ b1,
                             const float* __restrict__ W2l,
                             const float* __restrict__ W2r) {
    int warp = (blockIdx.x * blockDim.x + threadIdx.x) >> 5;
    if (warp >= NN) return;
    int lane = threadIdx.x & 31;
    int h = lane & 3;            // head / float4 index
    int eg = lane >> 2;          // edge slot 0..7

    // preload layer-2 weights for this lane's output column
    float w2[16];
#pragma unroll
    for (int k = 0; k < 16; k++) {
        if (lane < 8)       w2[k] = __ldg(W2l + k * 8 + lane);
        else if (lane < 16) w2[k] = __ldg(W2r + k * 8 + (lane - 8));
        else                w2[k] = 0.0f;
    }

    int d = warp;
    int cnt = g_cnt[d];
    int len = cnt < K_SLOT ? cnt : K_SLOT;
    const int* ep = g_esrc2 + d * K_SLOT;

    float4 aa = __ldg((const float4*)a1 + h);
    float4 xr = *((const float4*)(g_xr1 + d * 16) + h);

    float4 acc = make_float4(0.f, 0.f, 0.f, 0.f);
    float den = 0.0f;
    int lenUp = (len + 7) & ~7;
#pragma unroll 2
    for (int j = eg; j < lenUp; j += 8) {
        bool valid = j < len;
        int s = valid ? ep[j] : 0;
        float4 xl = *((const float4*)(g_xl1 + s * 16) + h);
        float lg = aa.x * lrelu02(xl.x + xr.x)
                 + aa.y * lrelu02(xl.y + xr.y)
                 + aa.z * lrelu02(xl.z + xr.z)
                 + aa.w * lrelu02(xl.w + xr.w);
        float ex = valid ? __expf(lg) : 0.0f;
        den += ex;
        acc.x = fmaf(ex, xl.x, acc.x);
        acc.y = fmaf(ex, xl.y, acc.y);
        acc.z = fmaf(ex, xl.z, acc.z);
        acc.w = fmaf(ex, xl.w, acc.w);
    }
    // spill fallback (empty in practice); lanes 0-3 process extra edges
    if (cnt > K_SLOT) {
        int ns = g_spill_cnt; if (ns > SPILL_MAX) ns = SPILL_MAX;
        for (int q = 0; q < ns; q++) {
            if (g_spill_d[q] == d && eg == 0) {
                int s = g_spill_s[q];
                float4 xl = *((const float4*)(g_xl1 + s * 16) + h);
                float lg = aa.x * lrelu02(xl.x + xr.x)
                         + aa.y * lrelu02(xl.y + xr.y)
                         + aa.z * lrelu02(xl.z + xr.z)
                         + aa.w * lrelu02(xl.w + xr.w);
                float ex = __expf(lg);
                den += ex;
                acc.x = fmaf(ex, xl.x, acc.x);
                acc.y = fmaf(ex, xl.y, acc.y);
                acc.z = fmaf(ex, xl.z, acc.z);
                acc.w = fmaf(ex, xl.w, acc.w);
            }
        }
    }
    // reduce across 8 edge groups (lanes with same h share channels)
#pragma unroll
    for (int o = 4; o < 32; o <<= 1) {
        acc.x += __shfl_xor_sync(0xFFFFFFFFu, acc.x, o);
        acc.y += __shfl_xor_sync(0xFFFFFFFFu, acc.y, o);
        acc.z += __shfl_xor_sync(0xFFFFFFFFu, acc.z, o);
        acc.w += __shfl_xor_sync(0xFFFFFFFFu, acc.w, o);
        den   += __shfl_xor_sync(0xFFFFFFFFu, den, o);
    }

    // fused node2: normalize + bias + ELU (every lane has its head's result)
    float inv = 1.0f / (den + 1e-16f);
    float4 bb = __ldg((const float4*)b1 + h);
    float v4[4];
    {
        float t0 = acc.x * inv + bb.x;
        float t1 = acc.y * inv + bb.y;
        float t2 = acc.z * inv + bb.z;
        float t3 = acc.w * inv + bb.w;
        v4[0] = (t0 > 0.0f) ? t0 : (__expf(t0) - 1.0f);
        v4[1] = (t1 > 0.0f) ? t1 : (__expf(t1) - 1.0f);
        v4[2] = (t2 > 0.0f) ? t2 : (__expf(t2) - 1.0f);
        v4[3] = (t3 > 0.0f) ? t3 : (__expf(t3) - 1.0f);
    }
    // 16-wide transform: v[k] lives in lane (k>>2) (replicated mod 4), reg k&3
    float o = 0.0f;
#pragma unroll
    for (int k = 0; k < 16; k++) {
        float vk = __shfl_sync(0xFFFFFFFFu, v4[k & 3], k >> 2);
        o = fmaf(vk, w2[k], o);
    }
    if (lane < 8)       g_xl2[d * 8 + lane] = o;
    else if (lane < 16) g_xr2[d * 8 + (lane - 8)] = o;
}

// ---------------- K5: edge layer 2 — 2 lanes per edge, fused output --------
__global__ void edge2_kernel(const float* __restrict__ a2,
                             const float* __restrict__ b2,
                             float* __restrict__ out) {
    int warp = (blockIdx.x * blockDim.x + threadIdx.x) >> 5;
    if (warp >= NN) return;
    int lane = threadIdx.x & 31;
    int hf = lane & 1;           // which float4 half of the 8 channels
    int eg = lane >> 1;          // edge slot 0..15

    int d = warp;
    int cnt = g_cnt[d];
    int len = cnt < K_SLOT ? cnt : K_SLOT;
    const int* ep = g_esrc2 + d * K_SLOT;

    float4 aa = __ldg((const float4*)a2 + hf);
    float4 xr = *((const float4*)(g_xr2 + d * 8) + hf);

    float4 acc = make_float4(0.f, 0.f, 0.f, 0.f);
    float den = 0.0f;
    int lenUp = (len + 15) & ~15;
#pragma unroll 2
    for (int j = eg; j < lenUp; j += 16) {
        bool valid = j < len;
        int s = valid ? ep[j] : 0;
        float4 xl = *((const float4*)(g_xl2 + s * 8) + hf);
        float t = aa.x * lrelu02(xl.x + xr.x)
                + aa.y * lrelu02(xl.y + xr.y)
                + aa.z * lrelu02(xl.z + xr.z)
                + aa.w * lrelu02(xl.w + xr.w);
        t += __shfl_xor_sync(0xFFFFFFFFu, t, 1);
        float ex = valid ? __expf(t) : 0.0f;
        den += ex;
        acc.x = fmaf(ex, xl.x, acc.x);
        acc.y = fmaf(ex, xl.y, acc.y);
        acc.z = fmaf(ex, xl.z, acc.z);
        acc.w = fmaf(ex, xl.w, acc.w);
    }
    if (cnt > K_SLOT) {
        int ns = g_spill_cnt; if (ns > SPILL_MAX) ns = SPILL_MAX;
        for (int q = 0; q < ns; q++) {
            if (g_spill_d[q] == d && eg == 0) {
                int s = g_spill_s[q];
                float4 xl = *((const float4*)(g_xl2 + s * 8) + hf);
                float t = aa.x * lrelu02(xl.x + xr.x)
                        + aa.y * lrelu02(xl.y + xr.y)
                        + aa.z * lrelu02(xl.z + xr.z)
                        + aa.w * lrelu02(xl.w + xr.w);
                t += __shfl_xor_sync(0x3u, t, 1);
                float ex = __expf(t);
                den += ex;
                acc.x = fmaf(ex, xl.x, acc.x);
                acc.y = fmaf(ex, xl.y, acc.y);
                acc.z = fmaf(ex, xl.z, acc.z);
                acc.w = fmaf(ex, xl.w, acc.w);
            }
        }
    }
    // reduce across 16 edge groups (keep the lane pair distinct: skip xor 1)
#pragma unroll
    for (int o = 2; o < 32; o <<= 1) {
        acc.x += __shfl_xor_sync(0xFFFFFFFFu, acc.x, o);
        acc.y += __shfl_xor_sync(0xFFFFFFFFu, acc.y, o);
        acc.z += __shfl_xor_sync(0xFFFFFFFFu, acc.z, o);
        acc.w += __shfl_xor_sync(0xFFFFFFFFu, acc.w, o);
        den   += __shfl_xor_sync(0xFFFFFFFFu, den, o);
    }

    if (lane < 2) {   // lane 0: channels 0-3, lane 1: channels 4-7
        float inv = 1.0f / (den + 1e-16f);
        float4 bb = __ldg((const float4*)b2 + lane);
        float4 r;
        r.x = 1.0f / (1.0f + __expf(-(acc.x * inv + bb.x)));
        r.y = 1.0f / (1.0f + __expf(-(acc.y * inv + bb.y)));
        r.z = 1.0f / (1.0f + __expf(-(acc.z * inv + bb.z)));
        r.w = 1.0f / (1.0f + __expf(-(acc.w * inv + bb.w)));
        *((float4*)(out + d * 8) + lane) = r;
    }
}

// ---------------- launch ----------------
extern "C" void kernel_launch(void* const* d_in, const int* in_sizes, int n_in,
                              void* d_out, int out_size) {
    const float* x   = (const float*)d_in[0];
    const void*  ei  = d_in[1];
    const float* W1l = (const float*)d_in[2];
    const float* W1r = (const float*)d_in[3];
    const float* a1  = (const float*)d_in[4];
    const float* b1  = (const float*)d_in[5];
    const float* W2l = (const float*)d_in[6];
    const float* W2r = (const float*)d_in[7];
    const float* a2  = (const float*)d_in[8];
    const float* b2  = (const float*)d_in[9];
    float* out = (float*)d_out;

    static bool configured = false;
    static cudaStream_t s2;
    static cudaEvent_t evA, evB;
    if (!configured) {
        cudaFuncSetAttribute(gemm1_kernel,
                             cudaFuncAttributeMaxDynamicSharedMemorySize,
                             (int)G_SMEM);
        cudaStreamCreateWithFlags(&s2, cudaStreamNonBlocking);
        cudaEventCreateWithFlags(&evA, cudaEventDisableTiming);
        cudaEventCreateWithFlags(&evB, cudaEventDisableTiming);
        configured = true;
    }

    const int EB = (EE + 255) / 256;
    const int NWB = (NN * 32 + 255) / 256;

    // fork: gemm1 on s2 in parallel with CSR build on default stream
    cudaEventRecord(evA, 0);
    cudaStreamWaitEvent(s2, evA, 0);
    gemm1_kernel<<<(NN + G_NODES - 1) / G_NODES, 256, G_SMEM, s2>>>(x, W1l, W1r);
    cudaEventRecord(evB, s2);

    init_kernel<<<(NN + 1023) / 1024, 1024>>>((const long long*)ei);
    build_kernel<<<EB, 256>>>(ei);

    // join
    cudaStreamWaitEvent(0, evB, 0);
    edge1_kernel<<<NWB, 256>>>(a1, b1, W2l, W2r);
    edge2_kernel<<<NWB, 256>>>(a2, b2, out);
}